// round 10
// baseline (speedup 1.0000x reference)
#include <cuda_runtime.h>
#include <math_constants.h>

// Chamfer distance, B=16 events, P=Q=4096, 3D.
// R10: compute the distance matrix ONCE (was: once per direction).
// Queries = gen rows (registers), candidates = gt cols (smem tile).
// Row-mins -> dir0 (per-row running min). Col-mins -> dir1 via
// redux.sync.min.u32 on float bits (d>=0 so bit order == float order;
// min is exact -> deterministic) + smem atomicMin + global atomicMin.
// Halves the FMA work: the measured wall across R4-R9 is the fp32 FMA
// datapath (packed f32x2 = 2 scalar-FMA slots).

#define NB 16
#define NP 4096
#define THREADS 256
#define RPT 2
#define ROWS (THREADS * RPT)          // 512 gen rows per block
#define CHUNKS (NP / ROWS)            // 8
#define CSPLIT 2
#define TQC (NP / CSPLIT)             // 2048 gt cols per block
#define NMIN (2 * NB * NP)            // 131072 mins (gen rows + gt cols)
#define INF_BITS 0x7F800000u

#define THREADS2 256
#define BLOCKS2 128
#define PER_BLOCK2 (NMIN / BLOCKS2)               // 1024
#define PER_THREAD2 (PER_BLOCK2 / THREADS2)       // 4

__device__ unsigned int g_min[NMIN];   // float bits; atomicMin-merged
__device__ float g_part2[BLOCKS2];
__device__ unsigned int g_sync2;       // zero-init; reset by combine

typedef unsigned long long u64;

__device__ __forceinline__ u64 pack2(float lo, float hi) {
    u64 r;
    asm("mov.b64 %0, {%1, %2};" : "=l"(r) : "f"(lo), "f"(hi));
    return r;
}
__device__ __forceinline__ u64 ffma2(u64 a, u64 b, u64 c) {
    u64 r;
    asm("fma.rn.f32x2 %0, %1, %2, %3;" : "=l"(r) : "l"(a), "l"(b), "l"(c));
    return r;
}
__device__ __forceinline__ u64 add2(u64 a, u64 b) {
    u64 r;
    asm("add.rn.f32x2 %0, %1, %2;" : "=l"(r) : "l"(a), "l"(b));
    return r;
}
__device__ __forceinline__ void unpack2(u64 v, float& lo, float& hi) {
    asm("mov.b64 {%0, %1}, %2;" : "=f"(lo), "=f"(hi) : "l"(v));
}
__device__ __forceinline__ unsigned int redux_min(unsigned int v) {
    unsigned int r;
    asm("redux.sync.min.u32 %0, %1, 0xffffffff;" : "=r"(r) : "r"(v));
    return r;
}

__global__ void init_kernel() {
    int i = blockIdx.x * blockDim.x + threadIdx.x;
    g_min[i] = INF_BITS;               // grid sized to cover NMIN exactly
}

__global__ __launch_bounds__(THREADS)
void chamfer_kernel(const float* __restrict__ gen,
                    const float* __restrict__ label) {
    // gt candidate quad per col-pair j: {(-2x0,-2x1),(-2y0,-2y1),(-2z0,-2z1),(n0,n1)}
    __shared__ __align__(16) float tile[TQC / 2 + 1][8];   // 32KB + 32B pad
    __shared__ unsigned int colmin_s[TQC];                  // 8KB

    const int split = blockIdx.z;      // col half
    const int b     = blockIdx.y;
    const int chunk = blockIdx.x;
    const int t     = threadIdx.x;
    const int lane  = t & 31;

    const float inv128 = 1.0f / 128.0f;

    // ---- gen query rows, register resident ----
    u64 xp0[RPT], xp1[RPT], xp2[RPT], xnp[RPT];
    float mlo[RPT], mhi[RPT];
#pragma unroll
    for (int r = 0; r < RPT; r++) {
        int row = b * NP + chunk * ROWS + r * THREADS + t;
        const float* s = gen + (size_t)row * 3;
        float px = s[0], py = s[1], pz = s[2];
        float xn = px * px + py * py + pz * pz;
        xp0[r] = pack2(px, px);
        xp1[r] = pack2(py, py);
        xp2[r] = pack2(pz, pz);
        xnp[r] = pack2(xn, xn);
        mlo[r] = CUDART_INF_F;
        mhi[r] = CUDART_INF_F;
    }

    // ---- init smem colmin + load gt candidate half into smem ----
#pragma unroll
    for (int p = t; p < TQC; p += THREADS) {
        colmin_s[p] = INF_BITS;
        int idx = b * NP + split * TQC + p;
        const float* s = label + (size_t)idx * 5 + 1;
        float cx = (s[0] - 128.0f) * inv128;
        float cy = (s[1] - 128.0f) * inv128;
        float cz = (s[2] - 128.0f) * inv128;
        int j = p >> 1, h = p & 1;
        tile[j][0 + h] = -2.0f * cx;
        tile[j][2 + h] = -2.0f * cy;
        tile[j][4 + h] = -2.0f * cz;
        tile[j][6 + h] = cx * cx + cy * cy + cz * cz;
    }
    __syncthreads();

    const ulonglong2* tp = (const ulonglong2*)tile;

    // software pipeline: prefetch next col-pair while computing current
    ulonglong2 c0 = tp[0];
    ulonglong2 c1 = tp[1];
#pragma unroll 8
    for (int j = 0; j < TQC / 2; j++) {
        ulonglong2 n0 = tp[j * 2 + 2];   // last iter reads the pad quad
        ulonglong2 n1 = tp[j * 2 + 3];

        // full d = (cn + xn) - 2 c.x  (per row r, packed over 2 cols)
        u64 d0 = ffma2(xp2[0], c1.x,
                 ffma2(xp1[0], c0.y,
                 ffma2(xp0[0], c0.x, add2(c1.y, xnp[0]))));
        u64 d1 = ffma2(xp2[1], c1.x,
                 ffma2(xp1[1], c0.y,
                 ffma2(xp0[1], c0.x, add2(c1.y, xnp[1]))));

        float lo0, hi0, lo1, hi1;
        unpack2(d0, lo0, hi0);
        unpack2(d1, lo1, hi1);

        // row mins (dir0)
        mlo[0] = fminf(mlo[0], lo0);
        mhi[0] = fminf(mhi[0], hi0);
        mlo[1] = fminf(mlo[1], lo1);
        mhi[1] = fminf(mhi[1], hi1);

        // col mins (dir1): min over this thread's rows, then cross-lane
        float vlo = fminf(lo0, lo1);
        float vhi = fminf(hi0, hi1);
        unsigned int rlo = redux_min(__float_as_uint(vlo));
        unsigned int rhi = redux_min(__float_as_uint(vhi));
        if (lane == 0) {
            atomicMin(&colmin_s[2 * j],     rlo);
            atomicMin(&colmin_s[2 * j + 1], rhi);
        }

        c0 = n0;
        c1 = n1;
    }

    // ---- merge row mins to global (across the 2 col-split blocks) ----
#pragma unroll
    for (int r = 0; r < RPT; r++) {
        int row = b * NP + chunk * ROWS + r * THREADS + t;
        float m = fminf(mlo[r], mhi[r]);
        atomicMin(&g_min[row], __float_as_uint(m));
    }

    // ---- merge col mins to global (across the 8 row-chunk blocks) ----
    __syncthreads();
#pragma unroll
    for (int p = t; p < TQC; p += THREADS) {
        int col = b * NP + split * TQC + p;
        atomicMin(&g_min[NB * NP + col], colmin_s[p]);
    }
}

__global__ __launch_bounds__(THREADS2)
void combine_kernel(float* __restrict__ out) {
    __shared__ float red[THREADS2 / 32];
    __shared__ unsigned int is_last;
    const int t = threadIdx.x;
    const int blk = blockIdx.x;

    float s = 0.0f;
#pragma unroll
    for (int i = 0; i < PER_THREAD2; i++) {
        int idx = blk * PER_BLOCK2 + i * THREADS2 + t;
        s += __uint_as_float(__ldcg(&g_min[idx]));
    }

#pragma unroll
    for (int o = 16; o > 0; o >>= 1)
        s += __shfl_down_sync(0xffffffffu, s, o);
    if ((t & 31) == 0) red[t >> 5] = s;
    __syncthreads();
    if (t == 0) {
        float tot = 0.0f;
#pragma unroll
        for (int w = 0; w < THREADS2 / 32; w++) tot += red[w];
        g_part2[blk] = tot;
        __threadfence();
        unsigned int v = atomicAdd(&g_sync2, 1u);
        is_last = (v == (unsigned int)(BLOCKS2 - 1)) ? 1u : 0u;
    }
    __syncthreads();

    if (is_last) {
        __threadfence();
        float ps = (t < BLOCKS2) ? __ldcg(&g_part2[t]) : 0.0f;
#pragma unroll
        for (int o = 16; o > 0; o >>= 1)
            ps += __shfl_down_sync(0xffffffffu, ps, o);
        if ((t & 31) == 0) red[t >> 5] = ps;
        __syncthreads();
        if (t == 0) {
            float tot = 0.0f;
#pragma unroll
            for (int w = 0; w < THREADS2 / 32; w++) tot += red[w];
            out[0] = tot * (1.0f / 65536.0f);   // / (P * B), P == Q
            g_sync2 = 0u;                       // reset for next call
        }
    }
}

extern "C" void kernel_launch(void* const* d_in, const int* in_sizes, int n_in,
                              void* d_out, int out_size) {
    const float* gen   = (const float*)d_in[0];  // [B*P, 3]
    // d_in[1] = batch_gen (int32), unused: contiguous equal segments
    const float* label = (const float*)d_in[2];  // [B*Q, 5]
    float* out = (float*)d_out;

    init_kernel<<<NMIN / 256, 256>>>();
    dim3 grid(CHUNKS, NB, CSPLIT);
    chamfer_kernel<<<grid, THREADS>>>(gen, label);
    combine_kernel<<<BLOCKS2, THREADS2>>>(out);
}